// round 9
// baseline (speedup 1.0000x reference)
#include <cuda_runtime.h>
#include <cuda_fp16.h>
#include <cstdint>

// ---------------------------------------------------------------------------
// Device scratch (allocation-free)
// ---------------------------------------------------------------------------
__device__ __align__(256) float g_vp[2 * 256 * 1024];  // partial v (+bias in z=0)
__device__ __align__(256) float g_sp[64 * 256];        // partial dots
__device__ int g_c1 = 0;                                // grid barrier arrivals
__device__ int g_c2 = 0;                                // finalizer completions

// ---------------------------------------------------------------------------
// Helpers
// ---------------------------------------------------------------------------
__device__ __forceinline__ uint32_t smem_u32(const void* p) {
    uint32_t a;
    asm("{ .reg .u64 t; cvta.to.shared.u64 t, %1; cvt.u32.u64 %0, t; }"
        : "=r"(a) : "l"(p));
    return a;
}

__device__ __forceinline__ void ldsm_x4(uint32_t* r, uint32_t addr) {
    asm volatile("ldmatrix.sync.aligned.m8n8.x4.shared.b16 {%0,%1,%2,%3}, [%4];"
                 : "=r"(r[0]), "=r"(r[1]), "=r"(r[2]), "=r"(r[3])
                 : "r"(addr));
}

__device__ __forceinline__ void sts128(uint32_t addr, uint4 v) {
    asm volatile("st.shared.v4.b32 [%0], {%1,%2,%3,%4};"
                 :: "r"(addr), "r"(v.x), "r"(v.y), "r"(v.z), "r"(v.w) : "memory");
}

__device__ __forceinline__ void mma16816(float* d, const uint32_t* a,
                                         uint32_t b0, uint32_t b1) {
    asm volatile(
        "mma.sync.aligned.m16n8k16.row.col.f32.f16.f16.f32 "
        "{%0,%1,%2,%3}, {%4,%5,%6,%7}, {%8,%9}, {%0,%1,%2,%3};"
        : "+f"(d[0]), "+f"(d[1]), "+f"(d[2]), "+f"(d[3])
        : "r"(a[0]), "r"(a[1]), "r"(a[2]), "r"(a[3]), "r"(b0), "r"(b1));
}

__device__ __forceinline__ uint4 pack_hi8(const float4 a0, const float4 a1) {
    __half2 h0 = __floats2half2_rn(a0.x, a0.y);
    __half2 h1 = __floats2half2_rn(a0.z, a0.w);
    __half2 h2 = __floats2half2_rn(a1.x, a1.y);
    __half2 h3 = __floats2half2_rn(a1.z, a1.w);
    uint4 u;
    u.x = *reinterpret_cast<uint32_t*>(&h0);
    u.y = *reinterpret_cast<uint32_t*>(&h1);
    u.z = *reinterpret_cast<uint32_t*>(&h2);
    u.w = *reinterpret_cast<uint32_t*>(&h3);
    return u;
}

// ---------------------------------------------------------------------------
// Fused GEMM + epilogue + grid-barrier finalization (single launch).
// CTA: 64(M) x 64(N), 4 warps of 32x32. Grid (32, 4, 2) = 256 CTAs, all
// co-resident (occ 2 guaranteed by launch bounds + 32KB smem).
// ---------------------------------------------------------------------------
#define A_STAGE_B 8192
#define B_STAGE_B 8192

__global__ void __launch_bounds__(128, 2)
fused_kernel(const float* __restrict__ x32, const float* __restrict__ q,
             const float* __restrict__ bias, const float* __restrict__ W32,
             float* __restrict__ out) {
    __shared__ __align__(1024) char smemA[2 * A_STAGE_B];
    __shared__ __align__(1024) char smemB[2 * B_STAGE_B];
    __shared__ float s_sm[64];
    const uint32_t sbA = smem_u32(smemA);
    const uint32_t sbB = smem_u32(smemB);

    const int tid  = threadIdx.x;
    const int lane = tid & 31;
    const int wid  = tid >> 5;            // 0..3
    const int wy   = wid >> 1;            // warp m index (0/1)
    const int wx   = wid & 1;             // warp n index (0/1)
    const int gq   = lane >> 2;           // group id 0..7
    const int tq   = lane & 3;            // quad thread 0..3

    const int n0 = blockIdx.x * 64;       // 0..2047
    const int m0 = blockIdx.y * 64;       // 0..255
    const int z  = blockIdx.z;            // split-K half
    const int c0 = z * 8;

    float4 areg[4][2], breg[4][2];
    auto ldg_AB = [&](int c) {
        const int koff = c * 64;
        #pragma unroll
        for (int s = 0; s < 4; s++) {
            int u = tid + 128 * s;
            int r = u >> 3, j = u & 7;
            const float4* sa = reinterpret_cast<const float4*>(
                x32 + (m0 + r) * 1024 + koff + j * 8);
            const float4* sb = reinterpret_cast<const float4*>(
                W32 + (n0 + r) * 1024 + koff + j * 8);
            areg[s][0] = sa[0];
            areg[s][1] = sa[1];
            breg[s][0] = sb[0];
            breg[s][1] = sb[1];
        }
    };

    auto sts_AB = [&](int buf) {
        const uint32_t baseA = sbA + buf * A_STAGE_B;
        const uint32_t baseB = sbB + buf * B_STAGE_B;
        #pragma unroll
        for (int s = 0; s < 4; s++) {
            int u = tid + 128 * s;
            int r = u >> 3, j = u & 7;
            uint32_t swz = (uint32_t)((j ^ (r & 7)) << 4);
            sts128(baseA + r * 128 + swz, pack_hi8(areg[s][0], areg[s][1]));
            sts128(baseB + r * 128 + swz, pack_hi8(breg[s][0], breg[s][1]));
        }
    };

    float acc[2][4][4];
    #pragma unroll
    for (int mi = 0; mi < 2; mi++)
        #pragma unroll
        for (int nj = 0; nj < 4; nj++)
            #pragma unroll
            for (int e = 0; e < 4; e++)
                acc[mi][nj][e] = 0.0f;

    ldg_AB(c0 + 0);

    const int lrow = lane & 15;
    const int lcb  = lane >> 4;

    for (int i = 0; i < 8; i++) {
        const int buf = i & 1;

        sts_AB(buf);
        if (i + 1 < 8) ldg_AB(c0 + i + 1);

        __syncthreads();

        const uint32_t sa = sbA + buf * A_STAGE_B;
        const uint32_t sB = sbB + buf * B_STAGE_B;

        #pragma unroll
        for (int ks = 0; ks < 4; ks++) {
            const int j = ks * 2 + lcb;
            uint32_t a[2][4], b[2][4];
            #pragma unroll
            for (int mi = 0; mi < 2; mi++) {
                int r = wy * 32 + mi * 16 + lrow;
                ldsm_x4(a[mi], sa + r * 128 + ((j ^ (r & 7)) << 4));
            }
            #pragma unroll
            for (int nb = 0; nb < 2; nb++) {
                int r = wx * 32 + nb * 16 + lrow;
                ldsm_x4(b[nb], sB + r * 128 + ((j ^ (r & 7)) << 4));
            }
            #pragma unroll
            for (int mi = 0; mi < 2; mi++)
                #pragma unroll
                for (int nj = 0; nj < 4; nj++) {
                    const int nb = nj >> 1, sub = nj & 1;
                    mma16816(acc[mi][nj], a[mi], b[nb][sub], b[nb][sub + 2]);
                }
        }
        __syncthreads();
    }

    // ------------------------------------------------------------------
    // Epilogue: write partials. acc element (mi, nj, e):
    //   row = m0 + wy*32 + mi*16 + gq + (e>=2 ? 8 : 0)
    //   col = n0 + wx*32 + nj*8  + 2*tq + (e&1)
    // Bias added only by the z==0 half.
    // ------------------------------------------------------------------
    float2 bb[4];
    #pragma unroll
    for (int nj = 0; nj < 4; nj++) {
        if (z == 0) {
            const int col = n0 + wx * 32 + nj * 8 + 2 * tq;
            bb[nj] = *reinterpret_cast<const float2*>(bias + col);
        } else {
            bb[nj].x = 0.0f; bb[nj].y = 0.0f;
        }
    }

    if (n0 < 1024) {
        float part[4];
        #pragma unroll
        for (int mi = 0; mi < 2; mi++)
            #pragma unroll
            for (int rh = 0; rh < 2; rh++) {
                const int row = m0 + wy * 32 + mi * 16 + rh * 8 + gq;
                float s = 0.0f;
                #pragma unroll
                for (int nj = 0; nj < 4; nj++) {
                    const int col = n0 + wx * 32 + nj * 8 + 2 * tq;
                    float2 qq = *reinterpret_cast<const float2*>(q + row * 1024 + col);
                    s += (acc[mi][nj][rh * 2 + 0] + bb[nj].x) * qq.x;
                    s += (acc[mi][nj][rh * 2 + 1] + bb[nj].y) * qq.y;
                }
                part[mi * 2 + rh] = s;
            }
        #pragma unroll
        for (int sl = 0; sl < 4; sl++) {
            part[sl] += __shfl_xor_sync(0xFFFFFFFFu, part[sl], 1);
            part[sl] += __shfl_xor_sync(0xFFFFFFFFu, part[sl], 2);
        }
        if (tq == 0) {
            const int slot = z * 32 + blockIdx.x * 2 + wx;   // 0..63
            #pragma unroll
            for (int sl = 0; sl < 4; sl++) {
                const int row = m0 + wy * 32 + (sl >> 1) * 16 + (sl & 1) * 8 + gq;
                g_sp[slot * 256 + row] = part[sl];
            }
        }
    } else {
        float* vbase = g_vp + z * 256 * 1024;
        #pragma unroll
        for (int mi = 0; mi < 2; mi++)
            #pragma unroll
            for (int rh = 0; rh < 2; rh++) {
                const int row = m0 + wy * 32 + mi * 16 + rh * 8 + gq;
                #pragma unroll
                for (int nj = 0; nj < 4; nj++) {
                    const int col = (n0 - 1024) + wx * 32 + nj * 8 + 2 * tq;
                    float2 o;
                    o.x = acc[mi][nj][rh * 2 + 0] + bb[nj].x;
                    o.y = acc[mi][nj][rh * 2 + 1] + bb[nj].y;
                    *reinterpret_cast<float2*>(vbase + row * 1024 + col) = o;
                }
            }
    }

    // ------------------------------------------------------------------
    // Grid barrier: all 256 CTAs co-resident (occ 2), so spinning is safe.
    // ------------------------------------------------------------------
    __threadfence();
    __syncthreads();
    if (tid == 0) atomicAdd(&g_c1, 1);

    if (z == 0 && n0 >= 1024) {
        // Finalizer: wait for all partials
        if (tid == 0) {
            while (atomicAdd(&g_c1, 0) < 256) {}
        }
        __syncthreads();

        // s[row] for this CTA's 64 rows (fixed order -> deterministic)
        if (tid < 64) {
            const int row = m0 + tid;
            float s = 0.0f;
            #pragma unroll
            for (int j = 0; j < 64; j++) s += g_sp[j * 256 + row];
            s_sm[tid] = s;
        }
        __syncthreads();

        // out tile: rows m0..m0+63, cols (n0-1024)..+63
        const int vc0 = n0 - 1024;
        #pragma unroll
        for (int k2 = 0; k2 < 8; k2++) {
            const int idx = tid + 128 * k2;      // 0..1023 float4 units
            const int lr = idx >> 4, lc = idx & 15;
            const int row = m0 + lr;
            const float* p0 = g_vp + row * 1024 + vc0 + lc * 4;
            const float* p1 = g_vp + 256 * 1024 + row * 1024 + vc0 + lc * 4;
            float4 v0 = *reinterpret_cast<const float4*>(p0);
            float4 v1 = *reinterpret_cast<const float4*>(p1);
            const float s = s_sm[lr];
            float4 o;
            o.x = (v0.x + v1.x) * s;
            o.y = (v0.y + v1.y) * s;
            o.z = (v0.z + v1.z) * s;
            o.w = (v0.w + v1.w) * s;
            *reinterpret_cast<float4*>(out + row * 1024 + vc0 + lc * 4) = o;
        }

        // Completion + counter reset (graph-replay safe)
        __threadfence();
        __syncthreads();
        if (tid == 0) {
            atomicAdd(&g_c2, 1);
            if (blockIdx.x == 16 && blockIdx.y == 0) {
                while (atomicAdd(&g_c2, 0) < 64) {}
                atomicExch(&g_c1, 0);
                atomicExch(&g_c2, 0);
            }
        }
    }
}

// ---------------------------------------------------------------------------
extern "C" void kernel_launch(void* const* d_in, const int* in_sizes, int n_in,
                              void* d_out, int out_size) {
    const float* x  = (const float*)d_in[0];   // 256x1024
    const float* q  = (const float*)d_in[1];   // 256x1024
    const float* W  = (const float*)d_in[2];   // 2048x1024
    const float* bs = (const float*)d_in[3];   // 2048
    float* out = (float*)d_out;                // 256x1024

    fused_kernel<<<dim3(32, 4, 2), 128>>>(x, q, bs, W, out);
}